// round 2
// baseline (speedup 1.0000x reference)
#include <cuda_runtime.h>
#include <cuda_bf16.h>
#include <cstdint>

// Problem constants
#define BB 4
#define SS 2048
#define DD 1024
#define HH 16
#define DHD 64
#define MROWS (BB*SS)          // 8192

// -------- scratch (alloc-free rule: __device__ globals) --------
__device__ float g_Q[(size_t)MROWS * DD];
__device__ float g_K[(size_t)MROWS * DD];
__device__ float g_V[(size_t)MROWS * DD];
__device__ float g_C[(size_t)MROWS * DD];

// ============================================================================
// GEMM: C[m,n] = sum_k A[m,k]*B[k,n] + bias[n]
// A: MxK row-major, B: KxN row-major. BM=BN=128, BK=8, 8x8 microtile, 256 thr.
// M%128==0, N%128==0, K%8==0 guaranteed by problem shapes.
// ============================================================================
__global__ void __launch_bounds__(256) sgemm_bias_kernel(
    const float* __restrict__ A, const float* __restrict__ B,
    const float* __restrict__ bias, float* __restrict__ C,
    int M, int N, int K)
{
    const int BM = 128, BN = 128, BK = 8, TM = 8, TN = 8;
    __shared__ float As[BK][BM];
    __shared__ float Bs[BK][BN];

    const int tid  = threadIdx.x;
    const int brow = blockIdx.y * BM;
    const int bcol = blockIdx.x * BN;

    // A tile load: 128x8 floats; thread -> (row = tid/2, kcol = (tid%2)*4)
    const int aRow = tid >> 1;
    const int aCol = (tid & 1) * 4;
    // B tile load: 8x128 floats; thread -> (krow = tid/32, col = (tid%32)*4)
    const int bRow = tid >> 5;
    const int bCol = (tid & 31) * 4;

    const int tr = (tid >> 4) * TM;   // 0..120
    const int tc = (tid & 15) * TN;   // 0..120

    float acc[TM][TN];
    #pragma unroll
    for (int i = 0; i < TM; i++)
        #pragma unroll
        for (int j = 0; j < TN; j++) acc[i][j] = 0.f;

    const float* Aptr = A + (size_t)(brow + aRow) * K + aCol;
    const float* Bptr = B + (size_t)bRow * N + bcol + bCol;

    for (int k0 = 0; k0 < K; k0 += BK) {
        float4 a4 = *reinterpret_cast<const float4*>(Aptr + k0);
        As[aCol + 0][aRow] = a4.x;
        As[aCol + 1][aRow] = a4.y;
        As[aCol + 2][aRow] = a4.z;
        As[aCol + 3][aRow] = a4.w;
        float4 b4 = *reinterpret_cast<const float4*>(Bptr + (size_t)k0 * N);
        *reinterpret_cast<float4*>(&Bs[bRow][bCol]) = b4;
        __syncthreads();

        #pragma unroll
        for (int k = 0; k < BK; k++) {
            float ra[TM], rb[TN];
            #pragma unroll
            for (int i = 0; i < TM; i++) ra[i] = As[k][tr + i];
            #pragma unroll
            for (int j = 0; j < TN; j++) rb[j] = Bs[k][tc + j];
            #pragma unroll
            for (int i = 0; i < TM; i++)
                #pragma unroll
                for (int j = 0; j < TN; j++)
                    acc[i][j] += ra[i] * rb[j];
        }
        __syncthreads();
    }

    #pragma unroll
    for (int i = 0; i < TM; i++) {
        #pragma unroll
        for (int j = 0; j < TN; j += 4) {
            float4 o;
            o.x = acc[i][j + 0] + bias[bcol + tc + j + 0];
            o.y = acc[i][j + 1] + bias[bcol + tc + j + 1];
            o.z = acc[i][j + 2] + bias[bcol + tc + j + 2];
            o.w = acc[i][j + 3] + bias[bcol + tc + j + 3];
            *reinterpret_cast<float4*>(&C[(size_t)(brow + tr + i) * N + bcol + tc + j]) = o;
        }
    }
}

// ============================================================================
// Causal flash attention, fp32.
// Q/K/V laid out [B*S, H*DH] (projection GEMM output). One thread = one q row.
// Block: 128 threads = 128 q rows. K/V tiles 32 x 64 in smem (broadcast reads).
// Online softmax; causal => block visits 4*qblk+4 tiles only.
// ============================================================================
#define AT_BM 128
#define AT_BN 32

__global__ void __launch_bounds__(128) attn_kernel(
    const float* __restrict__ Q, const float* __restrict__ K,
    const float* __restrict__ V, float* __restrict__ O)
{
    const int qblk = blockIdx.x;        // 0..15
    const int h    = blockIdx.y;        // 0..15
    const int b    = blockIdx.z;        // 0..3
    const int tid  = threadIdx.x;
    const int qi   = qblk * AT_BM + tid;      // local q row within sequence

    const float scale = 0.125f;               // 1/sqrt(64)

    const float* Qp    = Q + ((size_t)(b * SS + qi)) * DD + h * DHD;
    const float* Kbase = K + ((size_t)(b * SS)) * DD + h * DHD;
    const float* Vbase = V + ((size_t)(b * SS)) * DD + h * DHD;

    float q[DHD];
    #pragma unroll
    for (int d = 0; d < DHD; d += 4) {
        float4 t = *reinterpret_cast<const float4*>(Qp + d);
        q[d + 0] = t.x * scale; q[d + 1] = t.y * scale;
        q[d + 2] = t.z * scale; q[d + 3] = t.w * scale;
    }

    float acc[DHD];
    #pragma unroll
    for (int d = 0; d < DHD; d++) acc[d] = 0.f;
    float m = -1e30f, l = 0.f;

    __shared__ float Ks[AT_BN][DHD];
    __shared__ float Vs[AT_BN][DHD];

    const int ntiles = qblk * (AT_BM / AT_BN) + (AT_BM / AT_BN); // 4*qblk+4

    for (int t0 = 0; t0 < ntiles; t0++) {
        const int k0 = t0 * AT_BN;
        __syncthreads();   // protect prev-iteration tile reads
        // load 32x64 K and V tiles: 2048 floats each; 128 thr x 4 float4
        for (int idx = tid * 4; idx < AT_BN * DHD; idx += 128 * 4) {
            int r = idx >> 6, c = idx & 63;
            *reinterpret_cast<float4*>(&Ks[r][c]) =
                *reinterpret_cast<const float4*>(Kbase + (size_t)(k0 + r) * DD + c);
            *reinterpret_cast<float4*>(&Vs[r][c]) =
                *reinterpret_cast<const float4*>(Vbase + (size_t)(k0 + r) * DD + c);
        }
        __syncthreads();

        float p[AT_BN];
        float mt = m;
        #pragma unroll 4
        for (int j = 0; j < AT_BN; j++) {
            float s = 0.f;
            #pragma unroll
            for (int d = 0; d < DHD; d += 4) {
                float4 kv = *reinterpret_cast<const float4*>(&Ks[j][d]);
                s += q[d] * kv.x + q[d + 1] * kv.y + q[d + 2] * kv.z + q[d + 3] * kv.w;
            }
            p[j] = (k0 + j <= qi) ? s : -1e30f;
            mt = fmaxf(mt, p[j]);
        }
        const float corr = __expf(m - mt);
        m = mt;
        float ls = 0.f;
        #pragma unroll
        for (int j = 0; j < AT_BN; j++) {
            p[j] = __expf(p[j] - mt);
            ls += p[j];
        }
        l = l * corr + ls;
        #pragma unroll
        for (int d = 0; d < DHD; d++) acc[d] *= corr;
        #pragma unroll 4
        for (int j = 0; j < AT_BN; j++) {
            const float pj = p[j];
            #pragma unroll
            for (int d = 0; d < DHD; d += 4) {
                float4 vv = *reinterpret_cast<const float4*>(&Vs[j][d]);
                acc[d + 0] += pj * vv.x; acc[d + 1] += pj * vv.y;
                acc[d + 2] += pj * vv.z; acc[d + 3] += pj * vv.w;
            }
        }
    }

    const float inv = 1.f / l;
    float* Op = O + ((size_t)(b * SS + qi)) * DD + h * DHD;
    #pragma unroll
    for (int d = 0; d < DHD; d += 4) {
        float4 o;
        o.x = acc[d + 0] * inv; o.y = acc[d + 1] * inv;
        o.z = acc[d + 2] * inv; o.w = acc[d + 3] * inv;
        *reinterpret_cast<float4*>(Op + d) = o;
    }
}

// ============================================================================
// launch
// ============================================================================
extern "C" void kernel_launch(void* const* d_in, const int* in_sizes, int n_in,
                              void* d_out, int out_size)
{
    const float* x  = (const float*)d_in[0];
    const float* Wq = (const float*)d_in[1];
    const float* bq = (const float*)d_in[2];
    const float* Wk = (const float*)d_in[3];
    const float* bk = (const float*)d_in[4];
    const float* Wv = (const float*)d_in[5];
    const float* bv = (const float*)d_in[6];
    const float* Wo = (const float*)d_in[7];
    const float* bo = (const float*)d_in[8];
    float* out = (float*)d_out;

    float *pQ, *pK, *pV, *pC;
    cudaGetSymbolAddress((void**)&pQ, g_Q);
    cudaGetSymbolAddress((void**)&pK, g_K);
    cudaGetSymbolAddress((void**)&pV, g_V);
    cudaGetSymbolAddress((void**)&pC, g_C);

    const int M = MROWS, N = DD, K = DD;
    dim3 gemm_grid(N / 128, M / 128);   // (8, 64)

    sgemm_bias_kernel<<<gemm_grid, 256>>>(x, Wq, bq, pQ, M, N, K);
    sgemm_bias_kernel<<<gemm_grid, 256>>>(x, Wk, bk, pK, M, N, K);
    sgemm_bias_kernel<<<gemm_grid, 256>>>(x, Wv, bv, pV, M, N, K);

    dim3 attn_grid(SS / AT_BM, HH, BB); // (16, 16, 4)
    attn_kernel<<<attn_grid, 128>>>(pQ, pK, pV, pC);

    sgemm_bias_kernel<<<gemm_grid, 256>>>(pC, Wo, bo, out, M, N, K);
}

// round 3
// speedup vs baseline: 1.6701x; 1.6701x over previous
#include <cuda_runtime.h>
#include <cuda_bf16.h>
#include <cstdint>

// Problem constants
#define BB 4
#define SS 2048
#define DD 1024
#define HH 16
#define DHD 64
#define MROWS (BB*SS)          // 8192

// -------- scratch (alloc-free rule: __device__ globals) --------
__device__ float g_Q[(size_t)MROWS * DD];
__device__ float g_K[(size_t)MROWS * DD];
__device__ float g_V[(size_t)MROWS * DD];
__device__ float g_C[(size_t)MROWS * DD];

// ============================================================================
// TF32 tensor-core GEMM: C[m,n] = sum_k A[m,k]*B[k,n] + bias[n]
// A: MxK row-major, B: KxN row-major (weights), fp32 in/out.
// CTA tile 128x128x32, 8 warps (2x4), warp tile 64x32, mma.m16n8k8.tf32.
// cp.async double-buffered smem. Padded layouts, fragment loads conflict-free:
//   As[m][k] stride 36 -> A-frag banks (4g+t)%32 all distinct
//   Bs[k][n] stride 136 -> B-frag banks (8t+g)%32 all distinct
// ============================================================================
#define GBM 128
#define GBN 128
#define GBK 32
#define SA 36            // As row stride (floats)
#define SB 136           // Bs row stride (floats)
#define ASZ (GBM*SA)     // floats per A stage = 4608
#define BSZ (GBK*SB)     // floats per B stage = 4352
#define GEMM_SMEM_BYTES (2*(ASZ+BSZ)*4)   // 71680

__device__ __forceinline__ uint32_t f2tf32(float f) {
    uint32_t u;
    asm("cvt.rna.tf32.f32 %0, %1;" : "=r"(u) : "f"(f));
    return u;
}

__device__ __forceinline__ void cp16(uint32_t dst, const void* src) {
    asm volatile("cp.async.cg.shared.global [%0], [%1], 16;" :: "r"(dst), "l"(src));
}

__device__ __forceinline__ void mma_tf32(float* c, const uint32_t* a, const uint32_t* b) {
    asm volatile(
        "mma.sync.aligned.m16n8k8.row.col.f32.tf32.tf32.f32 "
        "{%0,%1,%2,%3}, {%4,%5,%6,%7}, {%8,%9}, {%0,%1,%2,%3};"
        : "+f"(c[0]), "+f"(c[1]), "+f"(c[2]), "+f"(c[3])
        : "r"(a[0]), "r"(a[1]), "r"(a[2]), "r"(a[3]), "r"(b[0]), "r"(b[1]));
}

__global__ void __launch_bounds__(256, 2) gemm_tf32_kernel(
    const float* __restrict__ A, const float* __restrict__ B,
    const float* __restrict__ bias, float* __restrict__ C,
    int M, int N, int K)
{
    extern __shared__ float smem[];
    float* AsBase = smem;                 // 2 stages of ASZ
    float* BsBase = smem + 2 * ASZ;       // 2 stages of BSZ
    const uint32_t smem_u = (uint32_t)__cvta_generic_to_shared(smem);
    const uint32_t AsU = smem_u;
    const uint32_t BsU = smem_u + 2 * ASZ * 4;

    const int tid  = threadIdx.x;
    const int wid  = tid >> 5;
    const int lane = tid & 31;
    const int g    = lane >> 2;        // 0..7
    const int t    = lane & 3;         // 0..3
    const int wm   = (wid >> 2) * 64;  // warp row offset in CTA tile
    const int wn   = (wid & 3) * 32;   // warp col offset

    const int brow = blockIdx.y * GBM;
    const int bcol = blockIdx.x * GBN;

    const float* Ag = A + (size_t)brow * K;   // + k0 + ...
    const float* Bg = B + bcol;               // + (k0+r)*N + c

    // gmem->smem load index precompute
    // A: 128 rows x 32 floats = 1024 float4; thread i-th: idx = tid + i*256
    const int a_r0 = tid >> 3;            // row advance +32 per i
    const int a_c  = (tid & 7) * 4;
    // B: 32 rows x 128 floats = 1024 float4
    const int b_r0 = tid >> 5;            // row advance +8 per i
    const int b_c  = (tid & 31) * 4;

    float acc[4][4][4];
    #pragma unroll
    for (int i = 0; i < 4; i++)
        #pragma unroll
        for (int j = 0; j < 4; j++)
            #pragma unroll
            for (int r = 0; r < 4; r++) acc[i][j][r] = 0.f;

    const int NIT = K / GBK;

    // ---- prologue: stage 0 ----
    {
        const int k0 = 0;
        #pragma unroll
        for (int i = 0; i < 4; i++) {
            int r = a_r0 + i * 32;
            cp16(AsU + (uint32_t)((r * SA + a_c) * 4), Ag + (size_t)r * K + k0 + a_c);
        }
        #pragma unroll
        for (int i = 0; i < 4; i++) {
            int r = b_r0 + i * 8;
            cp16(BsU + (uint32_t)((r * SB + b_c) * 4), Bg + (size_t)(k0 + r) * N + b_c);
        }
        asm volatile("cp.async.commit_group;");
    }

    for (int it = 0; it < NIT; ++it) {
        // prefetch next stage
        if (it + 1 < NIT) {
            const int k0 = (it + 1) * GBK;
            const uint32_t as = AsU + (uint32_t)(((it + 1) & 1) * ASZ * 4);
            const uint32_t bs = BsU + (uint32_t)(((it + 1) & 1) * BSZ * 4);
            #pragma unroll
            for (int i = 0; i < 4; i++) {
                int r = a_r0 + i * 32;
                cp16(as + (uint32_t)((r * SA + a_c) * 4), Ag + (size_t)r * K + k0 + a_c);
            }
            #pragma unroll
            for (int i = 0; i < 4; i++) {
                int r = b_r0 + i * 8;
                cp16(bs + (uint32_t)((r * SB + b_c) * 4), Bg + (size_t)(k0 + r) * N + b_c);
            }
            asm volatile("cp.async.commit_group;");
            asm volatile("cp.async.wait_group 1;");
        } else {
            asm volatile("cp.async.wait_group 0;");
        }
        __syncthreads();

        const float* As_ = AsBase + (it & 1) * ASZ;
        const float* Bs_ = BsBase + (it & 1) * BSZ;

        #pragma unroll
        for (int kk = 0; kk < 4; ++kk) {
            uint32_t af[4][4], bf[4][2];
            #pragma unroll
            for (int mt = 0; mt < 4; ++mt) {
                const float* p = As_ + (size_t)(wm + mt * 16 + g) * SA + kk * 8 + t;
                af[mt][0] = f2tf32(p[0]);
                af[mt][1] = f2tf32(p[8 * SA]);
                af[mt][2] = f2tf32(p[4]);
                af[mt][3] = f2tf32(p[8 * SA + 4]);
            }
            #pragma unroll
            for (int nt = 0; nt < 4; ++nt) {
                const float* p = Bs_ + (size_t)(kk * 8 + t) * SB + wn + nt * 8 + g;
                bf[nt][0] = f2tf32(p[0]);
                bf[nt][1] = f2tf32(p[4 * SB]);
            }
            #pragma unroll
            for (int mt = 0; mt < 4; ++mt)
                #pragma unroll
                for (int nt = 0; nt < 4; ++nt)
                    mma_tf32(acc[mt][nt], af[mt], bf[nt]);
        }
        __syncthreads();
    }

    // ---- epilogue: bias + store ----
    #pragma unroll
    for (int nt = 0; nt < 4; ++nt) {
        const int col = bcol + wn + nt * 8 + 2 * t;
        const float2 bb = *reinterpret_cast<const float2*>(&bias[col]);
        #pragma unroll
        for (int mt = 0; mt < 4; ++mt) {
            const int r0 = brow + wm + mt * 16 + g;
            float2 v0, v1;
            v0.x = acc[mt][nt][0] + bb.x;
            v0.y = acc[mt][nt][1] + bb.y;
            v1.x = acc[mt][nt][2] + bb.x;
            v1.y = acc[mt][nt][3] + bb.y;
            *reinterpret_cast<float2*>(&C[(size_t)r0 * N + col]) = v0;
            *reinterpret_cast<float2*>(&C[(size_t)(r0 + 8) * N + col]) = v1;
        }
    }
}

// ============================================================================
// Causal flash attention, fp32 (unchanged from R1; mma conversion is next).
// ============================================================================
#define AT_BM 128
#define AT_BN 32

__global__ void __launch_bounds__(128) attn_kernel(
    const float* __restrict__ Q, const float* __restrict__ K,
    const float* __restrict__ V, float* __restrict__ O)
{
    const int qblk = blockIdx.x;
    const int h    = blockIdx.y;
    const int b    = blockIdx.z;
    const int tid  = threadIdx.x;
    const int qi   = qblk * AT_BM + tid;

    const float scale = 0.125f;

    const float* Qp    = Q + ((size_t)(b * SS + qi)) * DD + h * DHD;
    const float* Kbase = K + ((size_t)(b * SS)) * DD + h * DHD;
    const float* Vbase = V + ((size_t)(b * SS)) * DD + h * DHD;

    float q[DHD];
    #pragma unroll
    for (int d = 0; d < DHD; d += 4) {
        float4 tq = *reinterpret_cast<const float4*>(Qp + d);
        q[d + 0] = tq.x * scale; q[d + 1] = tq.y * scale;
        q[d + 2] = tq.z * scale; q[d + 3] = tq.w * scale;
    }

    float acc[DHD];
    #pragma unroll
    for (int d = 0; d < DHD; d++) acc[d] = 0.f;
    float m = -1e30f, l = 0.f;

    __shared__ float Ks[AT_BN][DHD];
    __shared__ float Vs[AT_BN][DHD];

    const int ntiles = qblk * (AT_BM / AT_BN) + (AT_BM / AT_BN);

    for (int t0 = 0; t0 < ntiles; t0++) {
        const int k0 = t0 * AT_BN;
        __syncthreads();
        for (int idx = tid * 4; idx < AT_BN * DHD; idx += 128 * 4) {
            int r = idx >> 6, c = idx & 63;
            *reinterpret_cast<float4*>(&Ks[r][c]) =
                *reinterpret_cast<const float4*>(Kbase + (size_t)(k0 + r) * DD + c);
            *reinterpret_cast<float4*>(&Vs[r][c]) =
                *reinterpret_cast<const float4*>(Vbase + (size_t)(k0 + r) * DD + c);
        }
        __syncthreads();

        float p[AT_BN];
        float mt = m;
        #pragma unroll 4
        for (int j = 0; j < AT_BN; j++) {
            float s = 0.f;
            #pragma unroll
            for (int d = 0; d < DHD; d += 4) {
                float4 kv = *reinterpret_cast<const float4*>(&Ks[j][d]);
                s += q[d] * kv.x + q[d + 1] * kv.y + q[d + 2] * kv.z + q[d + 3] * kv.w;
            }
            p[j] = (k0 + j <= qi) ? s : -1e30f;
            mt = fmaxf(mt, p[j]);
        }
        const float corr = __expf(m - mt);
        m = mt;
        float ls = 0.f;
        #pragma unroll
        for (int j = 0; j < AT_BN; j++) {
            p[j] = __expf(p[j] - mt);
            ls += p[j];
        }
        l = l * corr + ls;
        #pragma unroll
        for (int d = 0; d < DHD; d++) acc[d] *= corr;
        #pragma unroll 4
        for (int j = 0; j < AT_BN; j++) {
            const float pj = p[j];
            #pragma unroll
            for (int d = 0; d < DHD; d += 4) {
                float4 vv = *reinterpret_cast<const float4*>(&Vs[j][d]);
                acc[d + 0] += pj * vv.x; acc[d + 1] += pj * vv.y;
                acc[d + 2] += pj * vv.z; acc[d + 3] += pj * vv.w;
            }
        }
    }

    const float inv = 1.f / l;
    float* Op = O + ((size_t)(b * SS + qi)) * DD + h * DHD;
    #pragma unroll
    for (int d = 0; d < DHD; d += 4) {
        float4 o;
        o.x = acc[d + 0] * inv; o.y = acc[d + 1] * inv;
        o.z = acc[d + 2] * inv; o.w = acc[d + 3] * inv;
        *reinterpret_cast<float4*>(Op + d) = o;
    }
}

// ============================================================================
// launch
// ============================================================================
extern "C" void kernel_launch(void* const* d_in, const int* in_sizes, int n_in,
                              void* d_out, int out_size)
{
    const float* x  = (const float*)d_in[0];
    const float* Wq = (const float*)d_in[1];
    const float* bq = (const float*)d_in[2];
    const float* Wk = (const float*)d_in[3];
    const float* bk = (const float*)d_in[4];
    const float* Wv = (const float*)d_in[5];
    const float* bv = (const float*)d_in[6];
    const float* Wo = (const float*)d_in[7];
    const float* bo = (const float*)d_in[8];
    float* out = (float*)d_out;

    float *pQ, *pK, *pV, *pC;
    cudaGetSymbolAddress((void**)&pQ, g_Q);
    cudaGetSymbolAddress((void**)&pK, g_K);
    cudaGetSymbolAddress((void**)&pV, g_V);
    cudaGetSymbolAddress((void**)&pC, g_C);

    cudaFuncSetAttribute(gemm_tf32_kernel,
                         cudaFuncAttributeMaxDynamicSharedMemorySize,
                         GEMM_SMEM_BYTES);

    const int M = MROWS, N = DD, K = DD;
    dim3 gemm_grid(N / GBN, M / GBM);   // (8, 64)

    gemm_tf32_kernel<<<gemm_grid, 256, GEMM_SMEM_BYTES>>>(x, Wq, bq, pQ, M, N, K);
    gemm_tf32_kernel<<<gemm_grid, 256, GEMM_SMEM_BYTES>>>(x, Wk, bk, pK, M, N, K);
    gemm_tf32_kernel<<<gemm_grid, 256, GEMM_SMEM_BYTES>>>(x, Wv, bv, pV, M, N, K);

    dim3 attn_grid(SS / AT_BM, HH, BB); // (16, 16, 4)
    attn_kernel<<<attn_grid, 128>>>(pQ, pK, pV, pC);

    gemm_tf32_kernel<<<gemm_grid, 256, GEMM_SMEM_BYTES>>>(pC, Wo, bo, out, M, N, K);
}

// round 4
// speedup vs baseline: 3.9854x; 2.3863x over previous
#include <cuda_runtime.h>
#include <cuda_bf16.h>
#include <cstdint>

// Problem constants
#define BB 4
#define SS 2048
#define DD 1024
#define HH 16
#define DHD 64
#define MROWS (BB*SS)          // 8192

// -------- scratch (alloc-free rule: __device__ globals) --------
__device__ float g_Q[(size_t)MROWS * DD];
__device__ float g_K[(size_t)MROWS * DD];
__device__ float g_V[(size_t)MROWS * DD];
__device__ float g_C[(size_t)MROWS * DD];

// ============================================================================
// Shared mma helpers (validated fragment mappings)
// ============================================================================
__device__ __forceinline__ uint32_t f2tf32(float f) {
    uint32_t u;
    asm("cvt.rna.tf32.f32 %0, %1;" : "=r"(u) : "f"(f));
    return u;
}

__device__ __forceinline__ void cp16(uint32_t dst, const void* src) {
    asm volatile("cp.async.cg.shared.global [%0], [%1], 16;" :: "r"(dst), "l"(src));
}

__device__ __forceinline__ void mma_tf32(float* c, const uint32_t* a, const uint32_t* b) {
    asm volatile(
        "mma.sync.aligned.m16n8k8.row.col.f32.tf32.tf32.f32 "
        "{%0,%1,%2,%3}, {%4,%5,%6,%7}, {%8,%9}, {%0,%1,%2,%3};"
        : "+f"(c[0]), "+f"(c[1]), "+f"(c[2]), "+f"(c[3])
        : "r"(a[0]), "r"(a[1]), "r"(a[2]), "r"(a[3]), "r"(b[0]), "r"(b[1]));
}

// ============================================================================
// TF32 tensor-core GEMM (unchanged from R2): C = A*B + bias
// ============================================================================
#define GBM 128
#define GBN 128
#define GBK 32
#define SA 36
#define SB 136
#define ASZ (GBM*SA)
#define BSZ (GBK*SB)
#define GEMM_SMEM_BYTES (2*(ASZ+BSZ)*4)

__global__ void __launch_bounds__(256, 2) gemm_tf32_kernel(
    const float* __restrict__ A, const float* __restrict__ B,
    const float* __restrict__ bias, float* __restrict__ C,
    int M, int N, int K)
{
    extern __shared__ float smem[];
    float* AsBase = smem;
    float* BsBase = smem + 2 * ASZ;
    const uint32_t smem_u = (uint32_t)__cvta_generic_to_shared(smem);
    const uint32_t AsU = smem_u;
    const uint32_t BsU = smem_u + 2 * ASZ * 4;

    const int tid  = threadIdx.x;
    const int wid  = tid >> 5;
    const int lane = tid & 31;
    const int g    = lane >> 2;
    const int t    = lane & 3;
    const int wm   = (wid >> 2) * 64;
    const int wn   = (wid & 3) * 32;

    const int brow = blockIdx.y * GBM;
    const int bcol = blockIdx.x * GBN;

    const float* Ag = A + (size_t)brow * K;
    const float* Bg = B + bcol;

    const int a_r0 = tid >> 3;
    const int a_c  = (tid & 7) * 4;
    const int b_r0 = tid >> 5;
    const int b_c  = (tid & 31) * 4;

    float acc[4][4][4];
    #pragma unroll
    for (int i = 0; i < 4; i++)
        #pragma unroll
        for (int j = 0; j < 4; j++)
            #pragma unroll
            for (int r = 0; r < 4; r++) acc[i][j][r] = 0.f;

    const int NIT = K / GBK;

    {
        #pragma unroll
        for (int i = 0; i < 4; i++) {
            int r = a_r0 + i * 32;
            cp16(AsU + (uint32_t)((r * SA + a_c) * 4), Ag + (size_t)r * K + a_c);
        }
        #pragma unroll
        for (int i = 0; i < 4; i++) {
            int r = b_r0 + i * 8;
            cp16(BsU + (uint32_t)((r * SB + b_c) * 4), Bg + (size_t)r * N + b_c);
        }
        asm volatile("cp.async.commit_group;");
    }

    for (int it = 0; it < NIT; ++it) {
        if (it + 1 < NIT) {
            const int k0 = (it + 1) * GBK;
            const uint32_t as = AsU + (uint32_t)(((it + 1) & 1) * ASZ * 4);
            const uint32_t bs = BsU + (uint32_t)(((it + 1) & 1) * BSZ * 4);
            #pragma unroll
            for (int i = 0; i < 4; i++) {
                int r = a_r0 + i * 32;
                cp16(as + (uint32_t)((r * SA + a_c) * 4), Ag + (size_t)r * K + k0 + a_c);
            }
            #pragma unroll
            for (int i = 0; i < 4; i++) {
                int r = b_r0 + i * 8;
                cp16(bs + (uint32_t)((r * SB + b_c) * 4), Bg + (size_t)(k0 + r) * N + b_c);
            }
            asm volatile("cp.async.commit_group;");
            asm volatile("cp.async.wait_group 1;");
        } else {
            asm volatile("cp.async.wait_group 0;");
        }
        __syncthreads();

        const float* As_ = AsBase + (it & 1) * ASZ;
        const float* Bs_ = BsBase + (it & 1) * BSZ;

        #pragma unroll
        for (int kk = 0; kk < 4; ++kk) {
            uint32_t af[4][4], bf[4][2];
            #pragma unroll
            for (int mt = 0; mt < 4; ++mt) {
                const float* p = As_ + (size_t)(wm + mt * 16 + g) * SA + kk * 8 + t;
                af[mt][0] = f2tf32(p[0]);
                af[mt][1] = f2tf32(p[8 * SA]);
                af[mt][2] = f2tf32(p[4]);
                af[mt][3] = f2tf32(p[8 * SA + 4]);
            }
            #pragma unroll
            for (int nt = 0; nt < 4; ++nt) {
                const float* p = Bs_ + (size_t)(kk * 8 + t) * SB + wn + nt * 8 + g;
                bf[nt][0] = f2tf32(p[0]);
                bf[nt][1] = f2tf32(p[4 * SB]);
            }
            #pragma unroll
            for (int mt = 0; mt < 4; ++mt)
                #pragma unroll
                for (int nt = 0; nt < 4; ++nt)
                    mma_tf32(acc[mt][nt], af[mt], bf[nt]);
        }
        __syncthreads();
    }

    #pragma unroll
    for (int nt = 0; nt < 4; ++nt) {
        const int col = bcol + wn + nt * 8 + 2 * t;
        const float2 bb = *reinterpret_cast<const float2*>(&bias[col]);
        #pragma unroll
        for (int mt = 0; mt < 4; ++mt) {
            const int r0 = brow + wm + mt * 16 + g;
            float2 v0, v1;
            v0.x = acc[mt][nt][0] + bb.x;
            v0.y = acc[mt][nt][1] + bb.y;
            v1.x = acc[mt][nt][2] + bb.x;
            v1.y = acc[mt][nt][3] + bb.y;
            *reinterpret_cast<float2*>(&C[(size_t)r0 * N + col]) = v0;
            *reinterpret_cast<float2*>(&C[(size_t)(r0 + 8) * N + col]) = v1;
        }
    }
}

// ============================================================================
// Causal flash attention on tensor cores (tf32 mma).
// Per block: 64 q rows for one (b,h). 4 warps, warp w owns q rows [16w,16w+16).
// Per kv tile (64): S^T = K·Q^T (A=K natural smem, B=Qt regs), softmax over
// the m-dim of S^T fragments via xor-shuffles, P^T -> smem (warp-private
// columns), O += P·V with A-frags read straight from the P^T layout.
// Padded smem strides: Ks 68 (A-frag banks 4g+t), Vs/Qt/Pts 72 (banks 8t+g).
// ============================================================================
#define AT_SK 68
#define AT_SV 72
#define AT_SQ 72
#define ATTN_SMEM_BYTES ((64*AT_SK + 64*AT_SV + 64*AT_SQ)*4 + 512)

__global__ void __launch_bounds__(128) attn_mma_kernel(
    const float* __restrict__ Q, const float* __restrict__ K,
    const float* __restrict__ V, float* __restrict__ O)
{
    extern __shared__ uint32_t sm_u[];
    uint32_t* Ks = sm_u;                        // 64 x 68 (tf32 K, [kv][d])
    uint32_t* Vs = Ks + 64 * AT_SK;             // 64 x 72 (tf32 V, [kv][d])
    uint32_t* Qt = Vs + 64 * AT_SV;             // 64 x 72 (tf32 Q^T, [d][q]); reused as P^T
    float* corr_s = (float*)(Qt + 64 * AT_SQ);  // 64
    float* l_s    = corr_s + 64;                // 64

    const int qblk = blockIdx.x;
    const int h    = blockIdx.y;
    const int b    = blockIdx.z;
    const int tid  = threadIdx.x;
    const int w    = tid >> 5;
    const int lane = tid & 31;
    const int g    = lane >> 2;   // 0..7
    const int t    = lane & 3;    // 0..3
    const int q0   = qblk * 64;

    const float* Qg = Q + ((size_t)(b * SS + q0)) * DD + h * DHD;
    const float* Kg = K + ((size_t)(b * SS)) * DD + h * DHD;
    const float* Vg = V + ((size_t)(b * SS)) * DD + h * DHD;

    // ---- Q^T into smem (scale folded, tf32). Once per block. ----
    #pragma unroll
    for (int i = 0; i < 8; i++) {
        int idx = tid + i * 128;
        int qr = idx & 63, c4 = (idx >> 6) * 4;
        float4 v = *reinterpret_cast<const float4*>(Qg + (size_t)qr * DD + c4);
        Qt[(c4 + 0) * AT_SQ + qr] = f2tf32(v.x * 0.125f);
        Qt[(c4 + 1) * AT_SQ + qr] = f2tf32(v.y * 0.125f);
        Qt[(c4 + 2) * AT_SQ + qr] = f2tf32(v.z * 0.125f);
        Qt[(c4 + 3) * AT_SQ + qr] = f2tf32(v.w * 0.125f);
    }
    __syncthreads();

    // ---- Q B-fragments into registers (warp w: q cols [16w,16w+16)) ----
    uint32_t qf[2][8][2];
    #pragma unroll
    for (int nt = 0; nt < 2; nt++)
        #pragma unroll
        for (int kk = 0; kk < 8; kk++) {
            int base = (kk * 8 + t) * AT_SQ + w * 16 + nt * 8 + g;
            qf[nt][kk][0] = Qt[base];
            qf[nt][kk][1] = Qt[base + 4 * AT_SQ];
        }

    float m[4], l[4];
    #pragma unroll
    for (int j = 0; j < 4; j++) { m[j] = -1e30f; l[j] = 0.f; }
    float oc[8][4];
    #pragma unroll
    for (int nt = 0; nt < 8; nt++)
        #pragma unroll
        for (int r = 0; r < 4; r++) oc[nt][r] = 0.f;

    uint32_t* Pts = Qt;  // reuse after qf consumed (guarded by loop-top sync)

    const int ntiles = qblk + 1;
    for (int tt = 0; tt < ntiles; tt++) {
        __syncthreads();   // prev tile fully consumed (also: qf loads done before 1st Pts write)
        // ---- load K,V tile (coalesced), convert tf32, conflict-free STS ----
        const float* Ktg = Kg + (size_t)(tt * 64) * DD;
        const float* Vtg = Vg + (size_t)(tt * 64) * DD;
        #pragma unroll
        for (int i = 0; i < 8; i++) {
            int idx = tid + i * 128;
            int r = idx >> 4, c4 = (idx & 15) * 4;
            float4 kv4 = *reinterpret_cast<const float4*>(Ktg + (size_t)r * DD + c4);
            Ks[r * AT_SK + c4 + 0] = f2tf32(kv4.x);
            Ks[r * AT_SK + c4 + 1] = f2tf32(kv4.y);
            Ks[r * AT_SK + c4 + 2] = f2tf32(kv4.z);
            Ks[r * AT_SK + c4 + 3] = f2tf32(kv4.w);
            float4 vv4 = *reinterpret_cast<const float4*>(Vtg + (size_t)r * DD + c4);
            Vs[r * AT_SV + c4 + 0] = f2tf32(vv4.x);
            Vs[r * AT_SV + c4 + 1] = f2tf32(vv4.y);
            Vs[r * AT_SV + c4 + 2] = f2tf32(vv4.z);
            Vs[r * AT_SV + c4 + 3] = f2tf32(vv4.w);
        }
        __syncthreads();

        // ---- S^T[kv][q] = K · Q^T ----
        float sc[4][2][4];
        #pragma unroll
        for (int mt = 0; mt < 4; mt++)
            #pragma unroll
            for (int nt = 0; nt < 2; nt++)
                #pragma unroll
                for (int r = 0; r < 4; r++) sc[mt][nt][r] = 0.f;

        #pragma unroll
        for (int mt = 0; mt < 4; mt++) {
            #pragma unroll
            for (int kk = 0; kk < 8; kk++) {
                uint32_t af[4];
                int base = (mt * 16 + g) * AT_SK + kk * 8 + t;
                af[0] = Ks[base];
                af[1] = Ks[base + 8 * AT_SK];
                af[2] = Ks[base + 4];
                af[3] = Ks[base + 8 * AT_SK + 4];
                #pragma unroll
                for (int nt = 0; nt < 2; nt++)
                    mma_tf32(sc[mt][nt], af, qf[nt][kk]);
            }
        }

        // ---- causal mask (diagonal tile only; k0 == q0 there) ----
        if (tt == qblk) {
            #pragma unroll
            for (int mt = 0; mt < 4; mt++)
                #pragma unroll
                for (int nt = 0; nt < 2; nt++)
                    #pragma unroll
                    for (int rh = 0; rh < 2; rh++)
                        #pragma unroll
                        for (int c = 0; c < 2; c++) {
                            int kv = mt * 16 + g + rh * 8;
                            int qq = w * 16 + nt * 8 + 2 * t + c;
                            if (kv > qq) sc[mt][nt][rh * 2 + c] = -1e30f;
                        }
        }

        // ---- online softmax over kv (m-dim): shuffle-reduce over g lanes ----
        float corr_loc[4];
        #pragma unroll
        for (int nt = 0; nt < 2; nt++)
            #pragma unroll
            for (int c = 0; c < 2; c++) {
                const int j = nt * 2 + c;
                float tmax = -1e30f;
                #pragma unroll
                for (int mt = 0; mt < 4; mt++) {
                    tmax = fmaxf(tmax, sc[mt][nt][c]);
                    tmax = fmaxf(tmax, sc[mt][nt][2 + c]);
                }
                tmax = fmaxf(tmax, __shfl_xor_sync(0xffffffffu, tmax, 4));
                tmax = fmaxf(tmax, __shfl_xor_sync(0xffffffffu, tmax, 8));
                tmax = fmaxf(tmax, __shfl_xor_sync(0xffffffffu, tmax, 16));
                const float mnew = fmaxf(m[j], tmax);
                corr_loc[j] = __expf(m[j] - mnew);
                m[j] = mnew;
                float ts = 0.f;
                #pragma unroll
                for (int mt = 0; mt < 4; mt++) {
                    float e0 = __expf(sc[mt][nt][c] - mnew);
                    float e1 = __expf(sc[mt][nt][2 + c] - mnew);
                    sc[mt][nt][c] = e0;
                    sc[mt][nt][2 + c] = e1;
                    ts += e0 + e1;
                }
                ts += __shfl_xor_sync(0xffffffffu, ts, 4);
                ts += __shfl_xor_sync(0xffffffffu, ts, 8);
                ts += __shfl_xor_sync(0xffffffffu, ts, 16);
                l[j] = l[j] * corr_loc[j] + ts;
            }

        // exchange per-q-row corr within warp via smem
        if (g == 0) {
            #pragma unroll
            for (int nt = 0; nt < 2; nt++)
                #pragma unroll
                for (int c = 0; c < 2; c++)
                    corr_s[w * 16 + nt * 8 + 2 * t + c] = corr_loc[nt * 2 + c];
        }
        // ---- P^T -> smem (tf32), warp-private columns ----
        #pragma unroll
        for (int mt = 0; mt < 4; mt++)
            #pragma unroll
            for (int nt = 0; nt < 2; nt++)
                #pragma unroll
                for (int rh = 0; rh < 2; rh++) {
                    int row = mt * 16 + g + rh * 8;
                    int col = w * 16 + nt * 8 + 2 * t;
                    Pts[row * AT_SQ + col]     = f2tf32(sc[mt][nt][rh * 2 + 0]);
                    Pts[row * AT_SQ + col + 1] = f2tf32(sc[mt][nt][rh * 2 + 1]);
                }
        __syncwarp();

        const float cr0 = corr_s[w * 16 + g];
        const float cr1 = corr_s[w * 16 + g + 8];
        #pragma unroll
        for (int nt = 0; nt < 8; nt++) {
            oc[nt][0] *= cr0; oc[nt][1] *= cr0;
            oc[nt][2] *= cr1; oc[nt][3] *= cr1;
        }

        // ---- O += P · V ----
        #pragma unroll
        for (int kk = 0; kk < 8; kk++) {
            uint32_t af[4];
            int base = (kk * 8 + t) * AT_SQ + w * 16 + g;
            af[0] = Pts[base];
            af[1] = Pts[base + 8];
            af[2] = Pts[base + 4 * AT_SQ];
            af[3] = Pts[base + 4 * AT_SQ + 8];
            #pragma unroll
            for (int nt = 0; nt < 8; nt++) {
                uint32_t bf[2];
                int vb = (kk * 8 + t) * AT_SV + nt * 8 + g;
                bf[0] = Vs[vb];
                bf[1] = Vs[vb + 4 * AT_SV];
                mma_tf32(oc[nt], af, bf);
            }
        }
    }

    // ---- epilogue: divide by l, store ----
    if (g == 0) {
        #pragma unroll
        for (int nt = 0; nt < 2; nt++)
            #pragma unroll
            for (int c = 0; c < 2; c++)
                l_s[w * 16 + nt * 8 + 2 * t + c] = l[nt * 2 + c];
    }
    __syncwarp();
    const float li0 = 1.f / l_s[w * 16 + g];
    const float li1 = 1.f / l_s[w * 16 + g + 8];

    float* Og = O + ((size_t)(b * SS + q0 + w * 16)) * DD + h * DHD;
    #pragma unroll
    for (int nt = 0; nt < 8; nt++) {
        const int col = nt * 8 + 2 * t;
        float2 v0, v1;
        v0.x = oc[nt][0] * li0; v0.y = oc[nt][1] * li0;
        v1.x = oc[nt][2] * li1; v1.y = oc[nt][3] * li1;
        *reinterpret_cast<float2*>(Og + (size_t)g * DD + col) = v0;
        *reinterpret_cast<float2*>(Og + (size_t)(g + 8) * DD + col) = v1;
    }
}

// ============================================================================
// launch
// ============================================================================
extern "C" void kernel_launch(void* const* d_in, const int* in_sizes, int n_in,
                              void* d_out, int out_size)
{
    const float* x  = (const float*)d_in[0];
    const float* Wq = (const float*)d_in[1];
    const float* bq = (const float*)d_in[2];
    const float* Wk = (const float*)d_in[3];
    const float* bk = (const float*)d_in[4];
    const float* Wv = (const float*)d_in[5];
    const float* bv = (const float*)d_in[6];
    const float* Wo = (const float*)d_in[7];
    const float* bo = (const float*)d_in[8];
    float* out = (float*)d_out;

    float *pQ, *pK, *pV, *pC;
    cudaGetSymbolAddress((void**)&pQ, g_Q);
    cudaGetSymbolAddress((void**)&pK, g_K);
    cudaGetSymbolAddress((void**)&pV, g_V);
    cudaGetSymbolAddress((void**)&pC, g_C);

    cudaFuncSetAttribute(gemm_tf32_kernel,
                         cudaFuncAttributeMaxDynamicSharedMemorySize,
                         GEMM_SMEM_BYTES);
    cudaFuncSetAttribute(attn_mma_kernel,
                         cudaFuncAttributeMaxDynamicSharedMemorySize,
                         ATTN_SMEM_BYTES);

    const int M = MROWS, N = DD, K = DD;
    dim3 gemm_grid(N / GBN, M / GBM);   // (8, 64)

    gemm_tf32_kernel<<<gemm_grid, 256, GEMM_SMEM_BYTES>>>(x, Wq, bq, pQ, M, N, K);
    gemm_tf32_kernel<<<gemm_grid, 256, GEMM_SMEM_BYTES>>>(x, Wk, bk, pK, M, N, K);
    gemm_tf32_kernel<<<gemm_grid, 256, GEMM_SMEM_BYTES>>>(x, Wv, bv, pV, M, N, K);

    dim3 attn_grid(SS / 64, HH, BB);    // (32, 16, 4)
    attn_mma_kernel<<<attn_grid, 128, ATTN_SMEM_BYTES>>>(pQ, pK, pV, pC);

    gemm_tf32_kernel<<<gemm_grid, 256, GEMM_SMEM_BYTES>>>(pC, Wo, bo, out, M, N, K);
}

// round 7
// speedup vs baseline: 4.1888x; 1.0510x over previous
#include <cuda_runtime.h>
#include <cuda_bf16.h>
#include <cstdint>

// Problem constants
#define BB 4
#define SS 2048
#define DD 1024
#define HH 16
#define DHD 64
#define MROWS (BB*SS)          // 8192

// -------- scratch (alloc-free rule: __device__ globals) --------
__device__ __align__(128) uint32_t g_xc[(size_t)MROWS * DD];        // x as tf32
__device__ __align__(128) uint32_t g_wqkv[(size_t)DD * 3 * DD];     // [k][3N] tf32
__device__ __align__(128) uint32_t g_wo[(size_t)DD * DD];           // [k][n] tf32
__device__ __align__(128) uint32_t g_QKV[(size_t)MROWS * 3 * DD];   // [m][3072] tf32
__device__ __align__(128) uint32_t g_ctx[(size_t)MROWS * DD];       // tf32

// ============================================================================
// helpers
// ============================================================================
__device__ __forceinline__ uint32_t f2tf32(float f) {
    uint32_t u;
    asm("cvt.rna.tf32.f32 %0, %1;" : "=r"(u) : "r"(__float_as_uint(f)));
    return u;
}

__device__ __forceinline__ void mma_tf32(float* c, const uint32_t* a, const uint32_t* b) {
    asm volatile(
        "mma.sync.aligned.m16n8k8.row.col.f32.tf32.tf32.f32 "
        "{%0,%1,%2,%3}, {%4,%5,%6,%7}, {%8,%9}, {%0,%1,%2,%3};"
        : "+f"(c[0]), "+f"(c[1]), "+f"(c[2]), "+f"(c[3])
        : "r"(a[0]), "r"(a[1]), "r"(a[2]), "r"(a[3]), "r"(b[0]), "r"(b[1]));
}

__device__ __forceinline__ void cp16(uint32_t dst, const void* src) {
    asm volatile("cp.async.cg.shared.global [%0], [%1], 16;" :: "r"(dst), "l"(src));
}

__device__ __forceinline__ uint32_t smem_u32(const void* p) {
    return (uint32_t)__cvta_generic_to_shared(p);
}

// ============================================================================
// prep: fp32 -> tf32(rna) conversions
// ============================================================================
__global__ void __launch_bounds__(256) conv_flat_kernel(
    const float* __restrict__ src, uint32_t* __restrict__ dst, int n4)
{
    int i = blockIdx.x * 256 + threadIdx.x;
    if (i >= n4) return;
    float4 v = reinterpret_cast<const float4*>(src)[i];
    uint4 o;
    o.x = f2tf32(v.x); o.y = f2tf32(v.y); o.z = f2tf32(v.z); o.w = f2tf32(v.w);
    reinterpret_cast<uint4*>(dst)[i] = o;
}

// W [1024][1024] -> dst rows stride ldo at column offset coff (tf32)
__global__ void __launch_bounds__(256) conv_w_kernel(
    const float* __restrict__ W, uint32_t* __restrict__ dst, int ldo, int coff)
{
    int i = blockIdx.x * 256 + threadIdx.x;   // 1024*256 float4s
    int k = i >> 8, n4 = (i & 255) * 4;
    float4 v = *reinterpret_cast<const float4*>(W + (size_t)k * DD + n4);
    uint4 o;
    o.x = f2tf32(v.x); o.y = f2tf32(v.y); o.z = f2tf32(v.z); o.w = f2tf32(v.w);
    *reinterpret_cast<uint4*>(dst + (size_t)k * ldo + coff + n4) = o;
}

// ============================================================================
// tf32 mma.sync GEMM, pre-converted operands.
// C[m,n] = sum_k A[m,k]*B[k,n] + bias[n]; A: Mx1024 tf32, B: 1024xN tf32.
// 128x128x32 CTA tile, 8 warps 64x32, double-buffered cp.async.
// OUT_TF32: store tf32 bit patterns (for downstream mma operands).
// ============================================================================
#define GBM 128
#define GBN 128
#define GBK 32
#define SA 36
#define SB 136
#define ASZ (GBM*SA)
#define BSZ (GBK*SB)
#define GEMM_SMEM_BYTES (2*(ASZ+BSZ)*4)

template<int OUT_TF32>
__global__ void __launch_bounds__(256, 2) gemm_tf32_kernel(
    const uint32_t* __restrict__ A, const uint32_t* __restrict__ B,
    const float* __restrict__ b0, const float* __restrict__ b1,
    const float* __restrict__ b2, void* __restrict__ Cv, int N)
{
    extern __shared__ uint32_t smem[];
    uint32_t* AsBase = smem;
    uint32_t* BsBase = smem + 2 * ASZ;
    const uint32_t smem_u = smem_u32(smem);
    const uint32_t AsU = smem_u;
    const uint32_t BsU = smem_u + 2 * ASZ * 4;

    const int K = DD;
    const int tid  = threadIdx.x;
    const int wid  = tid >> 5;
    const int lane = tid & 31;
    const int g    = lane >> 2;
    const int t    = lane & 3;
    const int wm   = (wid >> 2) * 64;
    const int wn   = (wid & 3) * 32;

    const int brow = blockIdx.y * GBM;
    const int bcol = blockIdx.x * GBN;

    const uint32_t* Ag = A + (size_t)brow * K;
    const uint32_t* Bg = B + bcol;

    const int a_r0 = tid >> 3;
    const int a_c  = (tid & 7) * 4;
    const int b_r0 = tid >> 5;
    const int b_c  = (tid & 31) * 4;

    float acc[4][4][4];
    #pragma unroll
    for (int i = 0; i < 4; i++)
        #pragma unroll
        for (int j = 0; j < 4; j++)
            #pragma unroll
            for (int r = 0; r < 4; r++) acc[i][j][r] = 0.f;

    const int NIT = K / GBK;

    {
        #pragma unroll
        for (int i = 0; i < 4; i++) {
            int r = a_r0 + i * 32;
            cp16(AsU + (uint32_t)((r * SA + a_c) * 4), Ag + (size_t)r * K + a_c);
        }
        #pragma unroll
        for (int i = 0; i < 4; i++) {
            int r = b_r0 + i * 8;
            cp16(BsU + (uint32_t)((r * SB + b_c) * 4), Bg + (size_t)r * N + b_c);
        }
        asm volatile("cp.async.commit_group;");
    }

    for (int it = 0; it < NIT; ++it) {
        if (it + 1 < NIT) {
            const int k0 = (it + 1) * GBK;
            const uint32_t as = AsU + (uint32_t)(((it + 1) & 1) * ASZ * 4);
            const uint32_t bs = BsU + (uint32_t)(((it + 1) & 1) * BSZ * 4);
            #pragma unroll
            for (int i = 0; i < 4; i++) {
                int r = a_r0 + i * 32;
                cp16(as + (uint32_t)((r * SA + a_c) * 4), Ag + (size_t)r * K + k0 + a_c);
            }
            #pragma unroll
            for (int i = 0; i < 4; i++) {
                int r = b_r0 + i * 8;
                cp16(bs + (uint32_t)((r * SB + b_c) * 4), Bg + (size_t)(k0 + r) * N + b_c);
            }
            asm volatile("cp.async.commit_group;");
            asm volatile("cp.async.wait_group 1;");
        } else {
            asm volatile("cp.async.wait_group 0;");
        }
        __syncthreads();

        const uint32_t* As_ = AsBase + (it & 1) * ASZ;
        const uint32_t* Bs_ = BsBase + (it & 1) * BSZ;

        #pragma unroll
        for (int kk = 0; kk < 4; ++kk) {
            uint32_t af[4][4], bf[4][2];
            #pragma unroll
            for (int mt = 0; mt < 4; ++mt) {
                const uint32_t* p = As_ + (size_t)(wm + mt * 16 + g) * SA + kk * 8 + t;
                af[mt][0] = p[0];
                af[mt][1] = p[8 * SA];
                af[mt][2] = p[4];
                af[mt][3] = p[8 * SA + 4];
            }
            #pragma unroll
            for (int nt = 0; nt < 4; ++nt) {
                const uint32_t* p = Bs_ + (size_t)(kk * 8 + t) * SB + wn + nt * 8 + g;
                bf[nt][0] = p[0];
                bf[nt][1] = p[4 * SB];
            }
            #pragma unroll
            for (int mt = 0; mt < 4; ++mt)
                #pragma unroll
                for (int nt = 0; nt < 4; ++nt)
                    mma_tf32(acc[mt][nt], af[mt], bf[nt]);
        }
        __syncthreads();
    }

    // epilogue: bias select (QKV fused tiles never straddle 1024 boundaries)
    const int bsel = bcol >> 10;
    const float* bias = (bsel == 0) ? b0 : (bsel == 1 ? b1 : b2);
    const int bloc = bcol & 1023;

    #pragma unroll
    for (int nt = 0; nt < 4; ++nt) {
        const int col = wn + nt * 8 + 2 * t;
        const float2 bb = *reinterpret_cast<const float2*>(&bias[bloc + col]);
        #pragma unroll
        for (int mt = 0; mt < 4; ++mt) {
            const int r0 = brow + wm + mt * 16 + g;
            float v00 = acc[mt][nt][0] + bb.x;
            float v01 = acc[mt][nt][1] + bb.y;
            float v10 = acc[mt][nt][2] + bb.x;
            float v11 = acc[mt][nt][3] + bb.y;
            if (OUT_TF32) {
                uint32_t* C = (uint32_t*)Cv;
                uint2 o0, o1;
                o0.x = f2tf32(v00); o0.y = f2tf32(v01);
                o1.x = f2tf32(v10); o1.y = f2tf32(v11);
                *reinterpret_cast<uint2*>(&C[(size_t)r0 * N + bcol + col]) = o0;
                *reinterpret_cast<uint2*>(&C[(size_t)(r0 + 8) * N + bcol + col]) = o1;
            } else {
                float* C = (float*)Cv;
                float2 o0, o1;
                o0.x = v00; o0.y = v01;
                o1.x = v10; o1.y = v11;
                *reinterpret_cast<float2*>(&C[(size_t)r0 * N + bcol + col]) = o0;
                *reinterpret_cast<float2*>(&C[(size_t)(r0 + 8) * N + bcol + col]) = o1;
            }
        }
    }
}

// ============================================================================
// Causal flash attention, tf32 mma.sync, pre-converted Q/K/V (from g_QKV).
// 256 threads, 128 q rows per block; warp w owns q cols [16w, 16w+16).
// kv tiles of 64 via cp.async. S^T = K * Q^T; softmax over m-dim via shuffles;
// P^T -> smem; O += P*V. Outputs ctx as tf32.
// Strides: Ks 68 (banks 4g+t), Vs 72 (8t+g), Qt/Pts 136 (8t+g). All 16B-aligned.
// ============================================================================
#define SKS 68
#define SVS 72
#define SQS 136
#define O_KS 0
#define O_VS (64*SKS)
#define O_QT (O_VS + 64*SVS)
#define O_PT (O_QT + 64*SQS)
#define O_CR (O_PT + 64*SQS)
#define O_LS (O_CR + 128)
#define ATTN_SMEM_BYTES ((O_LS + 128) * 4)    // 106496

__global__ void __launch_bounds__(256, 2) attn_mma_kernel(
    const uint32_t* __restrict__ QKV, uint32_t* __restrict__ Ctx)
{
    extern __shared__ uint32_t sm[];
    uint32_t* Ks = sm + O_KS;
    uint32_t* Vs = sm + O_VS;
    uint32_t* Qt = sm + O_QT;
    uint32_t* Pts = sm + O_PT;
    float* corr_s = (float*)(sm + O_CR);
    float* l_s    = (float*)(sm + O_LS);
    const uint32_t smb = smem_u32(sm);

    const int qblk = gridDim.x - 1 - blockIdx.x;   // high-work blocks first
    const int h    = blockIdx.y;
    const int b    = blockIdx.z;
    const int tid  = threadIdx.x;
    const int w    = tid >> 5;
    const int lane = tid & 31;
    const int g    = lane >> 2;
    const int t    = lane & 3;
    const int q0   = qblk * 128;

    const uint32_t* Qg = QKV + ((size_t)(b * SS + q0)) * 3072 + h * DHD;
    const uint32_t* Kg = QKV + ((size_t)(b * SS)) * 3072 + 1024 + h * DHD;
    const uint32_t* Vg = Kg + 1024;

    // ---- Q^T [d][q] into smem (scale 0.125 exact in tf32) ----
    #pragma unroll
    for (int i = 0; i < 8; i++) {
        int idx = tid + i * 256;
        int qr = idx & 127, c4 = (idx >> 7) * 4;
        uint4 v = *reinterpret_cast<const uint4*>(Qg + (size_t)qr * 3072 + c4);
        Qt[(c4 + 0) * SQS + qr] = __float_as_uint(__uint_as_float(v.x) * 0.125f);
        Qt[(c4 + 1) * SQS + qr] = __float_as_uint(__uint_as_float(v.y) * 0.125f);
        Qt[(c4 + 2) * SQS + qr] = __float_as_uint(__uint_as_float(v.z) * 0.125f);
        Qt[(c4 + 3) * SQS + qr] = __float_as_uint(__uint_as_float(v.w) * 0.125f);
    }

    float m[4], l[4];
    #pragma unroll
    for (int j = 0; j < 4; j++) { m[j] = -1e30f; l[j] = 0.f; }
    float oc[8][4];
    #pragma unroll
    for (int nt = 0; nt < 8; nt++)
        #pragma unroll
        for (int r = 0; r < 4; r++) oc[nt][r] = 0.f;

    // K/V tile load indices: 64 rows x 16 chunks of 16B
    const int kv_r = tid >> 4;
    const int kv_c = (tid & 15) * 4;

    const int ntiles = 2 * qblk + 2;
    for (int tt = 0; tt < ntiles; tt++) {
        __syncthreads();   // prev tile fully consumed (and Qt writes on tt=0)
        {
            const uint32_t* Ktg = Kg + (size_t)(tt * 64) * 3072;
            const uint32_t* Vtg = Vg + (size_t)(tt * 64) * 3072;
            #pragma unroll
            for (int i = 0; i < 4; i++) {
                const int r = kv_r + i * 16;
                cp16(smb + (uint32_t)((O_KS + r * SKS + kv_c) * 4), Ktg + (size_t)r * 3072 + kv_c);
                cp16(smb + (uint32_t)((O_VS + r * SVS + kv_c) * 4), Vtg + (size_t)r * 3072 + kv_c);
            }
            asm volatile("cp.async.commit_group;");
            asm volatile("cp.async.wait_group 0;");
        }
        __syncthreads();

        // ---- S^T[kv][q] = K * Q^T ----
        float sc[4][2][4];
        #pragma unroll
        for (int mt = 0; mt < 4; mt++)
            #pragma unroll
            for (int nt = 0; nt < 2; nt++)
                #pragma unroll
                for (int r = 0; r < 4; r++) sc[mt][nt][r] = 0.f;

        #pragma unroll
        for (int kk = 0; kk < 8; kk++) {
            uint32_t bfq[2][2];
            #pragma unroll
            for (int nt = 0; nt < 2; nt++) {
                const int base = (kk * 8 + t) * SQS + w * 16 + nt * 8 + g;
                bfq[nt][0] = Qt[base];
                bfq[nt][1] = Qt[base + 4 * SQS];
            }
            #pragma unroll
            for (int mt = 0; mt < 4; mt++) {
                uint32_t af[4];
                const int base = (mt * 16 + g) * SKS + kk * 8 + t;
                af[0] = Ks[base];
                af[1] = Ks[base + 8 * SKS];
                af[2] = Ks[base + 4];
                af[3] = Ks[base + 8 * SKS + 4];
                mma_tf32(sc[mt][0], af, bfq[0]);
                mma_tf32(sc[mt][1], af, bfq[1]);
            }
        }

        // ---- causal mask (only possible on last two tiles) ----
        if (tt >= 2 * qblk) {
            const int kvb = tt * 64;
            #pragma unroll
            for (int mt = 0; mt < 4; mt++)
                #pragma unroll
                for (int nt = 0; nt < 2; nt++)
                    #pragma unroll
                    for (int rh = 0; rh < 2; rh++)
                        #pragma unroll
                        for (int c = 0; c < 2; c++) {
                            int kv = kvb + mt * 16 + g + rh * 8;
                            int qq = q0 + w * 16 + nt * 8 + 2 * t + c;
                            if (kv > qq) sc[mt][nt][rh * 2 + c] = -1e30f;
                        }
        }

        // ---- online softmax over kv ----
        float corr_loc[4];
        #pragma unroll
        for (int nt = 0; nt < 2; nt++)
            #pragma unroll
            for (int c = 0; c < 2; c++) {
                const int j = nt * 2 + c;
                float tmax = -1e30f;
                #pragma unroll
                for (int mt = 0; mt < 4; mt++) {
                    tmax = fmaxf(tmax, sc[mt][nt][c]);
                    tmax = fmaxf(tmax, sc[mt][nt][2 + c]);
                }
                tmax = fmaxf(tmax, __shfl_xor_sync(0xffffffffu, tmax, 4));
                tmax = fmaxf(tmax, __shfl_xor_sync(0xffffffffu, tmax, 8));
                tmax = fmaxf(tmax, __shfl_xor_sync(0xffffffffu, tmax, 16));
                const float mnew = fmaxf(m[j], tmax);
                corr_loc[j] = __expf(m[j] - mnew);
                m[j] = mnew;
                float ts = 0.f;
                #pragma unroll
                for (int mt = 0; mt < 4; mt++) {
                    float e0 = __expf(sc[mt][nt][c] - mnew);
                    float e1 = __expf(sc[mt][nt][2 + c] - mnew);
                    sc[mt][nt][c] = e0;
                    sc[mt][nt][2 + c] = e1;
                    ts += e0 + e1;
                }
                ts += __shfl_xor_sync(0xffffffffu, ts, 4);
                ts += __shfl_xor_sync(0xffffffffu, ts, 8);
                ts += __shfl_xor_sync(0xffffffffu, ts, 16);
                l[j] = l[j] * corr_loc[j] + ts;
            }

        if (g == 0) {
            #pragma unroll
            for (int nt = 0; nt < 2; nt++)
                #pragma unroll
                for (int c = 0; c < 2; c++)
                    corr_s[w * 16 + nt * 8 + 2 * t + c] = corr_loc[nt * 2 + c];
        }
        // ---- P^T -> smem (tf32), warp-private columns ----
        #pragma unroll
        for (int mt = 0; mt < 4; mt++)
            #pragma unroll
            for (int nt = 0; nt < 2; nt++)
                #pragma unroll
                for (int rh = 0; rh < 2; rh++) {
                    int row = mt * 16 + g + rh * 8;
                    int col = w * 16 + nt * 8 + 2 * t;
                    Pts[row * SQS + col]     = f2tf32(sc[mt][nt][rh * 2 + 0]);
                    Pts[row * SQS + col + 1] = f2tf32(sc[mt][nt][rh * 2 + 1]);
                }
        __syncwarp();

        const float cr0 = corr_s[w * 16 + g];
        const float cr1 = corr_s[w * 16 + g + 8];
        #pragma unroll
        for (int nt = 0; nt < 8; nt++) {
            oc[nt][0] *= cr0; oc[nt][1] *= cr0;
            oc[nt][2] *= cr1; oc[nt][3] *= cr1;
        }

        // ---- O += P * V ----
        #pragma unroll
        for (int kk = 0; kk < 8; kk++) {
            uint32_t af[4];
            const int base = (kk * 8 + t) * SQS + w * 16 + g;
            af[0] = Pts[base];
            af[1] = Pts[base + 8];
            af[2] = Pts[base + 4 * SQS];
            af[3] = Pts[base + 4 * SQS + 8];
            #pragma unroll
            for (int nt = 0; nt < 8; nt++) {
                uint32_t bf[2];
                const int vb = (kk * 8 + t) * SVS + nt * 8 + g;
                bf[0] = Vs[vb];
                bf[1] = Vs[vb + 4 * SVS];
                mma_tf32(oc[nt], af, bf);
            }
        }
    }

    // ---- epilogue ----
    if (g == 0) {
        #pragma unroll
        for (int nt = 0; nt < 2; nt++)
            #pragma unroll
            for (int c = 0; c < 2; c++)
                l_s[w * 16 + nt * 8 + 2 * t + c] = l[nt * 2 + c];
    }
    __syncwarp();
    const float li0 = 1.f / l_s[w * 16 + g];
    const float li1 = 1.f / l_s[w * 16 + g + 8];

    uint32_t* Og = Ctx + ((size_t)(b * SS + q0 + w * 16)) * DD + h * DHD;
    #pragma unroll
    for (int nt = 0; nt < 8; nt++) {
        const int col = nt * 8 + 2 * t;
        uint2 v0, v1;
        v0.x = f2tf32(oc[nt][0] * li0); v0.y = f2tf32(oc[nt][1] * li0);
        v1.x = f2tf32(oc[nt][2] * li1); v1.y = f2tf32(oc[nt][3] * li1);
        *reinterpret_cast<uint2*>(Og + (size_t)g * DD + col) = v0;
        *reinterpret_cast<uint2*>(Og + (size_t)(g + 8) * DD + col) = v1;
    }
}

// ============================================================================
// launch
// ============================================================================
extern "C" void kernel_launch(void* const* d_in, const int* in_sizes, int n_in,
                              void* d_out, int out_size)
{
    const float* x  = (const float*)d_in[0];
    const float* Wq = (const float*)d_in[1];
    const float* bq = (const float*)d_in[2];
    const float* Wk = (const float*)d_in[3];
    const float* bk = (const float*)d_in[4];
    const float* Wv = (const float*)d_in[5];
    const float* bv = (const float*)d_in[6];
    const float* Wo = (const float*)d_in[7];
    const float* bo = (const float*)d_in[8];
    float* out = (float*)d_out;

    uint32_t *pxc, *pwqkv, *pwo, *pQKV, *pctx;
    cudaGetSymbolAddress((void**)&pxc, g_xc);
    cudaGetSymbolAddress((void**)&pwqkv, g_wqkv);
    cudaGetSymbolAddress((void**)&pwo, g_wo);
    cudaGetSymbolAddress((void**)&pQKV, g_QKV);
    cudaGetSymbolAddress((void**)&pctx, g_ctx);

    cudaFuncSetAttribute(gemm_tf32_kernel<1>,
                         cudaFuncAttributeMaxDynamicSharedMemorySize, GEMM_SMEM_BYTES);
    cudaFuncSetAttribute(gemm_tf32_kernel<0>,
                         cudaFuncAttributeMaxDynamicSharedMemorySize, GEMM_SMEM_BYTES);
    cudaFuncSetAttribute(attn_mma_kernel,
                         cudaFuncAttributeMaxDynamicSharedMemorySize, ATTN_SMEM_BYTES);

    // prep: convert x, weights to tf32 (weights Q|K|V concatenated per k-row)
    conv_flat_kernel<<<(MROWS * DD / 4 + 255) / 256, 256>>>(x, pxc, MROWS * DD / 4);
    conv_w_kernel<<<1024, 256>>>(Wq, pwqkv, 3 * DD, 0);
    conv_w_kernel<<<1024, 256>>>(Wk, pwqkv, 3 * DD, 1024);
    conv_w_kernel<<<1024, 256>>>(Wv, pwqkv, 3 * DD, 2048);
    conv_w_kernel<<<1024, 256>>>(Wo, pwo, DD, 0);

    // fused QKV projection: [8192 x 1024] * [1024 x 3072]
    dim3 qkv_grid(3 * DD / GBN, MROWS / GBM);   // (24, 64)
    gemm_tf32_kernel<1><<<qkv_grid, 256, GEMM_SMEM_BYTES>>>(
        pxc, pwqkv, bq, bk, bv, pQKV, 3 * DD);

    // attention
    dim3 attn_grid(SS / 128, HH, BB);           // (16, 16, 4)
    attn_mma_kernel<<<attn_grid, 256, ATTN_SMEM_BYTES>>>(pQKV, pctx);

    // output projection: [8192 x 1024] * [1024 x 1024] -> fp32 out
    dim3 out_grid(DD / GBN, MROWS / GBM);       // (8, 64)
    gemm_tf32_kernel<0><<<out_grid, 256, GEMM_SMEM_BYTES>>>(
        pctx, pwo, bo, bo, bo, out, DD);
}